// round 8
// baseline (speedup 1.0000x reference)
#include <cuda_runtime.h>
#include <cstdint>

#define BATCH 64
#define TLEN  512
#define D     1024

// ---------------- scratch (device globals: no allocations allowed) ----------------
__device__ float g_ext[(size_t)TLEN * BATCH * D];   // 128 MB, layout [t][b][o]
__device__ float g_stateA[BATCH * D];
__device__ float g_stateB[BATCH * D];
__device__ unsigned g_bars[4 * 32];                  // per-m-group barrier counters

typedef unsigned long long ULL;

// ---------------- packed f32x2 helpers (sm_103a FFMA2 path) ----------------
static __device__ __forceinline__ ULL pack2(float lo, float hi) {
    ULL r;
    asm("mov.b64 %0, {%1, %2};" : "=l"(r) : "f"(lo), "f"(hi));
    return r;
}
static __device__ __forceinline__ void fma2(ULL& d, ULL a, ULL b) {
    asm("fma.rn.f32x2 %0, %1, %2, %0;" : "+l"(d) : "l"(a), "l"(b));
}
static __device__ __forceinline__ void unpack2(ULL v, float& lo, float& hi) {
    asm("mov.b64 {%0, %1}, %2;" : "=f"(lo), "=f"(hi) : "l"(v));
}

// ---------------- trivial zero kernels ----------------
__global__ void zero4_kernel(float4* __restrict__ p, int n4) {
    int i = blockIdx.x * blockDim.x + threadIdx.x;
    if (i < n4) p[i] = make_float4(0.f, 0.f, 0.f, 0.f);
}
__global__ void zero_state_kernel() {
    int i = blockIdx.x * blockDim.x + threadIdx.x;
    if (i < BATCH * D) g_stateA[i] = 0.f;
    if (i < 4 * 32) g_bars[i] = 0u;
}

// ---------------- Phase A: ext[t][b][o] = sum_k x[m][k] * W_in[o][k], m=b*512+t --------
// k-pair-packed FFMA2 GEMM. BM=128, BN=64, BK=16, 256 threads, 8m x 4n per thread.
// A staged row-major [m][k] (float4 STS, no transpose); B staged as [kpair][n] ULLs.
// Inner loop: pure broadcast LDS.128 -> FFMA2 (no MOV duplication).
#define BM 128
#define BN 64
#define BK 16
#define AROW 20                          // floats per A row (16 + 4 pad, 16B aligned)
#define BROW 66                          // ULLs per B kpair row (64 + 2 pad)
#define A_STG (BM * AROW)                // 2560 floats = 10240 B
#define B_STG (8 * BROW)                 // 528 ULL    = 4224 B
#define A_OFF(s) ((s) * A_STG)
#define EXT_SMEM (2 * (A_STG * 4 + B_STG * 8))   // 28928 B

__global__ __launch_bounds__(256, 2) void ext_gemm_kernel(const float* __restrict__ X,
                                                          const float* __restrict__ Win) {
    extern __shared__ char esmc[];
    float* Af = (float*)esmc;                       // 2 stages of A
    ULL*   Bu = (ULL*)(esmc + 2 * A_STG * 4);       // 2 stages of B

    const int tid = threadIdx.x;
    const int Mb = blockIdx.y * BM;
    const int Nb = blockIdx.x * BN;
    const int ty = tid >> 4, tx = tid & 15;
    const int m0 = ty * 8, n0 = tx * 4;

    // loader mapping
    const int am = tid >> 1, aq = tid & 1;          // A: row am, float4 cols {2aq, 2aq+1}
    const int bn = tid >> 2, bq = tid & 3;          // B: row bn, float4 col bq
    const float* aSrc = X + (size_t)(Mb + am) * D + aq * 8;
    const float* bSrc = Win + (size_t)(Nb + bn) * D + bq * 4;

    ULL acc[8][4];
#pragma unroll
    for (int i = 0; i < 8; ++i)
#pragma unroll
        for (int j = 0; j < 4; ++j) acc[i][j] = 0ULL;

    // prologue: fetch tile 0
    float4 rA0 = *(const float4*)(aSrc);
    float4 rA1 = *(const float4*)(aSrc + 4);
    float4 rB  = *(const float4*)(bSrc);

#pragma unroll 2
    for (int kt = 0; kt < D / BK; ++kt) {
        const int s = kt & 1;

        // ---- stage regs -> smem ----
        {
            float* ad = Af + A_OFF(s) + am * AROW + aq * 8;
            *(float4*)(ad)     = rA0;
            *(float4*)(ad + 4) = rA1;
            ULL* bd = Bu + s * B_STG + (bq * 2) * BROW + bn;
            bd[0]    = pack2(rB.x, rB.y);
            bd[BROW] = pack2(rB.z, rB.w);
        }
        __syncthreads();

        // ---- fetch next tile ----
        if (kt < D / BK - 1) {
            const int k0 = (kt + 1) * BK;
            rA0 = *(const float4*)(aSrc + k0);
            rA1 = *(const float4*)(aSrc + k0 + 4);
            rB  = *(const float4*)(bSrc + k0);
        }

        // ---- compute this tile: 4 k-quads ----
        const float* ab = Af + A_OFF(s) + m0 * AROW;
        const ULL*   bb = Bu + s * B_STG + n0;
#pragma unroll
        for (int kq = 0; kq < 4; ++kq) {
            const ULL* br0 = bb + (kq * 2) * BROW;
            ulonglong2 b0a = *(const ulonglong2*)(br0);
            ulonglong2 b0b = *(const ulonglong2*)(br0 + 2);
            ulonglong2 b1a = *(const ulonglong2*)(br0 + BROW);
            ulonglong2 b1b = *(const ulonglong2*)(br0 + BROW + 2);
#pragma unroll
            for (int i = 0; i < 8; ++i) {
                ulonglong2 av = *(const ulonglong2*)(ab + i * AROW + kq * 4);
                fma2(acc[i][0], av.x, b0a.x); fma2(acc[i][1], av.x, b0a.y);
                fma2(acc[i][2], av.x, b0b.x); fma2(acc[i][3], av.x, b0b.y);
                fma2(acc[i][0], av.y, b1a.x); fma2(acc[i][1], av.y, b1a.y);
                fma2(acc[i][2], av.y, b1b.x); fma2(acc[i][3], av.y, b1b.y);
            }
        }
        __syncthreads();
    }

    // ---- epilogue: fold k-parity, store to g_ext [t][b][o] ----
#pragma unroll
    for (int i = 0; i < 8; ++i) {
        float v[4];
#pragma unroll
        for (int j = 0; j < 4; ++j) {
            float lo, hi;
            unpack2(acc[i][j], lo, hi);
            v[j] = lo + hi;
        }
        const int m = Mb + m0 + i;
        const int bi = m >> 9, ti = m & 511;
        *(float4*)&g_ext[((size_t)ti * BATCH + bi) * D + Nb + n0] =
            make_float4(v[0], v[1], v[2], v[3]);
    }
}

// ---------------- Phase B: persistent recurrence, W_rec in registers ----------------
// 256 threads (8 warps), launch_bounds(256,1) -> 255-reg budget, NO spills:
// W frag = 128 floats (64 f32x2 regs), acc[16] = 32 regs, ~200 total.
// Warp w owns k-slice [w*128, w*128+128); lane l owns column n = Nb+l.
// All compute-phase LDS are warp-uniform 16B broadcasts (1 crossbar phase).
#define NTILE 32
#define MTILE 16
#define SSTR  1028
#define PERS_SMEM ((MTILE * SSTR + 8 * 512) * 4)   // 82176 B

__global__ __launch_bounds__(256, 1) void rnn_persistent(const float* __restrict__ Wr) {
    extern __shared__ float sm[];
    float* sTile = sm;                   // [16][SSTR]
    float* red   = sm + MTILE * SSTR;    // [8 kgroups][16 m * 32 n]

    const int tid = threadIdx.x;
    const int w   = tid >> 5;            // warp = 128-wide k-slice (0..7)
    const int l   = tid & 31;            // lane = n
    const int Nb  = blockIdx.x * NTILE;
    const int Mb  = blockIdx.y * MTILE;
    unsigned* bar = &g_bars[blockIdx.y * 32];

    // staging mapping: row r (16 rows), 16 threads per row, 16 float4 each
    const int r  = tid >> 4;             // 0..15
    const int c0 = tid & 15;             // float4 column base

    // ---- W fragment -> registers (128 floats, held for all 512 steps) ----
    ULL w2[64];
    {
        const float* wp = Wr + (size_t)(Nb + l) * D + w * 128;
#pragma unroll
        for (int j = 0; j < 32; ++j) {
            ulonglong2 v = *(const ulonglong2*)(wp + 4 * j);
            w2[2 * j]     = v.x;
            w2[2 * j + 1] = v.y;
        }
    }

    // ---- preload ext[0] into s-tile (state0 == 0, so s = ext[0]) ----
    {
        const float4* esrc = (const float4*)(g_ext + (size_t)(Mb + r) * D);
        float* sdst = sTile + r * SSTR;
#pragma unroll
        for (int j = 0; j < 16; ++j) {
            const int q = c0 + j * 16;
            *(float4*)(sdst + q * 4) = __ldg(esrc + q);
        }
    }
    __syncthreads();

    for (int t = 0; t < TLEN; ++t) {
        float* sout = (t & 1) ? g_stateA : g_stateB;

        if (t > 0) {
            const float* sin = (t & 1) ? g_stateB : g_stateA;
            // ---- barrier: all CTAs in m-group finished step t-1 ----
            if (tid == 0) {
                const unsigned target = 32u * (unsigned)t;
                unsigned v;
                do {
                    asm volatile("ld.acquire.gpu.u32 %0, [%1];" : "=r"(v) : "l"(bar));
                } while (v < target);
            }
            __syncthreads();

            // ---- add state into prefetched ext tile ----
            const float4* ssrc = (const float4*)(sin + (size_t)(Mb + r) * D);
            float* sdst = sTile + r * SSTR;
#pragma unroll
            for (int j = 0; j < 16; j += 2) {
                const int q0 = c0 + j * 16;
                const int q1 = c0 + (j + 1) * 16;
                float4 a0 = __ldcg(ssrc + q0);
                float4 a1 = __ldcg(ssrc + q1);
                float4 b0 = *(const float4*)(sdst + q0 * 4);
                float4 b1 = *(const float4*)(sdst + q1 * 4);
                *(float4*)(sdst + q0 * 4) = make_float4(a0.x + b0.x, a0.y + b0.y, a0.z + b0.z, a0.w + b0.w);
                *(float4*)(sdst + q1 * 4) = make_float4(a1.x + b1.x, a1.y + b1.y, a1.z + b1.z, a1.w + b1.w);
            }
            __syncthreads();   // all rows staged before any warp computes
        }

        // ---- compute: acc[16 m] over this warp's 128-k slice (broadcast LDS) ----
        ULL acc[16];
#pragma unroll
        for (int i = 0; i < 16; ++i) acc[i] = 0ULL;

        const float* sb = sTile + w * 128;
#pragma unroll
        for (int m = 0; m < 16; ++m) {
            const ulonglong2* srow = (const ulonglong2*)(sb + (size_t)m * SSTR);
#pragma unroll
            for (int j = 0; j < 32; ++j) {
                ulonglong2 sv = srow[j];
                fma2(acc[m], sv.x, w2[2 * j]);
                fma2(acc[m], sv.y, w2[2 * j + 1]);
            }
        }

        // ---- fold k-parity, write partials (conflict-free) ----
#pragma unroll
        for (int m = 0; m < 16; ++m) {
            float lo, hi;
            unpack2(acc[m], lo, hi);
            red[w * 512 + m * 32 + l] = lo + hi;
        }
        __syncthreads();

        // ---- reduce over 8 k-slices, ReLU, write state (2 outputs/thread) ----
#pragma unroll
        for (int rep = 0; rep < 2; ++rep) {
            const int idx = tid + rep * 256;
            const int rm = idx >> 5, rn = idx & 31;
            float s0 = 0.f, s1 = 0.f;
#pragma unroll
            for (int g = 0; g < 8; g += 2) {
                s0 += red[g * 512 + idx];
                s1 += red[(g + 1) * 512 + idx];
            }
            __stcg(&sout[(size_t)(Mb + rm) * D + Nb + rn], fmaxf(s0 + s1, 0.f));
        }
        __syncthreads();   // all state writes done before arrive; sTile safe to overwrite

        // ---- arrive, then prefetch ext[t+1] (overlaps other CTAs' compute) ----
        if (tid == 0) {
            __threadfence();
            atomicAdd(bar, 1u);
        }
        if (t + 1 < TLEN) {
            const float4* esrc = (const float4*)(g_ext + (size_t)(t + 1) * (BATCH * D) + (size_t)(Mb + r) * D);
            float* sdst = sTile + r * SSTR;
#pragma unroll
            for (int j = 0; j < 16; ++j) {
                const int q = c0 + j * 16;
                *(float4*)(sdst + q * 4) = __ldg(esrc + q);
            }
        }
    }
}

// ---------------- final: out[:,0,:] = final state ----------------
__global__ void final_copy_kernel(float* __restrict__ out) {
    const int i = blockIdx.x * blockDim.x + threadIdx.x;   // < 65536
    const int b = i >> 10, o = i & 1023;
    out[(size_t)b * (TLEN * D) + o] = g_stateA[i];
}

// ---------------- launch ----------------
extern "C" void kernel_launch(void* const* d_in, const int* in_sizes, int n_in,
                              void* d_out, int out_size) {
    const float* x     = (const float*)d_in[0];
    const float* W_in  = (const float*)d_in[1];
    const float* W_rec = (const float*)d_in[2];
    float* out = (float*)d_out;

    cudaFuncSetAttribute(rnn_persistent, cudaFuncAttributeMaxDynamicSharedMemorySize, PERS_SMEM);
    cudaFuncSetAttribute(ext_gemm_kernel, cudaFuncAttributeMaxDynamicSharedMemorySize, EXT_SMEM);

    // zero output (poisoned by harness), initial state, barrier counters
    zero4_kernel<<<(BATCH * TLEN * D / 4 + 255) / 256, 256>>>((float4*)out, BATCH * TLEN * D / 4);
    zero_state_kernel<<<(BATCH * D + 255) / 256, 256>>>();

    // Phase A: input projections for all timesteps (ext layout [t][b][o])
    ext_gemm_kernel<<<dim3(D / BN, (BATCH * TLEN) / BM), 256, EXT_SMEM>>>(x, W_in);

    // Phase B: full recurrence in one persistent kernel
    rnn_persistent<<<dim3(D / NTILE, BATCH / MTILE), 256, PERS_SMEM>>>(W_rec);

    // write final state into out[:,0,:]
    final_copy_kernel<<<(BATCH * D) / 256, 256>>>(out);
}

// round 9
// speedup vs baseline: 1.1381x; 1.1381x over previous
#include <cuda_runtime.h>
#include <cstdint>

#define BATCH 64
#define TLEN  512
#define D     1024

// ---------------- scratch (device globals: no allocations allowed) ----------------
__device__ float g_ext[(size_t)TLEN * BATCH * D];   // 128 MB, layout [t][b][o]
__device__ float g_stateA[BATCH * D];
__device__ float g_stateB[BATCH * D];
__device__ unsigned g_bars[4 * 32];                  // per-m-group barrier counters

typedef unsigned long long ULL;

// ---------------- packed f32x2 helpers (sm_103a FFMA2 path) ----------------
static __device__ __forceinline__ ULL pack_dup(float w) {
    ULL r;
    asm("mov.b64 %0, {%1, %1};" : "=l"(r) : "f"(w));
    return r;
}
static __device__ __forceinline__ void fma2(ULL& d, ULL a, ULL b) {
    asm("fma.rn.f32x2 %0, %1, %2, %0;" : "+l"(d) : "l"(a), "l"(b));
}
static __device__ __forceinline__ void unpack2(ULL v, float& lo, float& hi) {
    asm("mov.b64 {%0, %1}, %2;" : "=f"(lo), "=f"(hi) : "l"(v));
}

// ---------------- trivial zero kernels ----------------
__global__ void zero4_kernel(float4* __restrict__ p, int n4) {
    int i = blockIdx.x * blockDim.x + threadIdx.x;
    if (i < n4) p[i] = make_float4(0.f, 0.f, 0.f, 0.f);
}
__global__ void zero_state_kernel() {
    int i = blockIdx.x * blockDim.x + threadIdx.x;
    if (i < BATCH * D) g_stateA[i] = 0.f;
    if (i < 4 * 32) g_bars[i] = 0u;
}

// ---------------- Phase A: ext[t][b][o] = sum_k x[m][k] * W_in[o][k], m=b*512+t --------
// m-pair-packed FFMA2 GEMM. BM=256, BN=64, BK=16, 256 threads, 16m x 4n per thread
// (32 ULL acc = 64 regs). Transposed smem tiles, double-buffered, ONE sync per tile.
// Per kk: 8 broadcast LDS.64 (A) + 1 LDS.128 (B) + 4 MOV + 32 FFMA2.
#define BM 256
#define BN 64
#define BK 16
#define AROWS 260                        // floats per As k-row (256 + 4 pad; 2-way max)
#define BROWS 68                         // floats per Bs k-row (64 + 4 pad)
#define A_STG (BK * AROWS)               // 4160 floats
#define B_STG (BK * BROWS)               // 1088 floats
#define EXT_SMEM (2 * (A_STG + B_STG) * 4)   // 41984 B

__global__ __launch_bounds__(256, 2) void ext_gemm_kernel(const float* __restrict__ X,
                                                          const float* __restrict__ Win) {
    extern __shared__ float esm[];
    float* As = esm;                     // 2 stages: As[k][m]
    float* Bs = esm + 2 * A_STG;         // 2 stages: Bs[k][n]

    const int tid = threadIdx.x;
    const int Mb = blockIdx.y * BM;
    const int Nb = blockIdx.x * BN;
    const int ty = tid >> 4, tx = tid & 15;
    const int m0 = ty * 16;              // 16 m rows (8 pairs)
    const int n0 = tx * 4;               // 4 n cols

    ULL acc[8][4];
#pragma unroll
    for (int i = 0; i < 8; ++i)
#pragma unroll
        for (int j = 0; j < 4; ++j) acc[i][j] = 0ULL;

    // loaders: A row ar+g*64 (g=0..3), float4 col aq; B row bn, float4 col bq
    const int ar = tid >> 2, aq = tid & 3;
    const int bn = tid >> 2, bq = tid & 3;
    const float* aSrc = X + (size_t)(Mb + ar) * D + aq * 4;
    const float* bSrc = Win + (size_t)(Nb + bn) * D + bq * 4;

    float4 ra[4], rb;
#pragma unroll
    for (int g = 0; g < 4; ++g)
        ra[g] = *(const float4*)(aSrc + (size_t)g * 64 * D);
    rb = *(const float4*)(bSrc);
    {
#pragma unroll
        for (int g = 0; g < 4; ++g) {
            const int m = ar + g * 64;
            As[(aq * 4 + 0) * AROWS + m] = ra[g].x;
            As[(aq * 4 + 1) * AROWS + m] = ra[g].y;
            As[(aq * 4 + 2) * AROWS + m] = ra[g].z;
            As[(aq * 4 + 3) * AROWS + m] = ra[g].w;
        }
        Bs[(bq * 4 + 0) * BROWS + bn] = rb.x;
        Bs[(bq * 4 + 1) * BROWS + bn] = rb.y;
        Bs[(bq * 4 + 2) * BROWS + bn] = rb.z;
        Bs[(bq * 4 + 3) * BROWS + bn] = rb.w;
    }
    __syncthreads();

    for (int kt = 0; kt < D / BK; ++kt) {
        const int s = kt & 1;
        const float* Ac = As + s * A_STG + m0;
        const float* Bc = Bs + s * B_STG + n0;

        // fetch next tile into registers (latency hidden by compute below)
        if (kt < D / BK - 1) {
            const int k0 = (kt + 1) * BK;
#pragma unroll
            for (int g = 0; g < 4; ++g)
                ra[g] = *(const float4*)(aSrc + (size_t)g * 64 * D + k0);
            rb = *(const float4*)(bSrc + k0);
        }

        // compute this tile
#pragma unroll
        for (int kk = 0; kk < BK; ++kk) {
            float4 bv = *(const float4*)(Bc + kk * BROWS);
            ULL b0 = pack_dup(bv.x);
            ULL b1 = pack_dup(bv.y);
            ULL b2 = pack_dup(bv.z);
            ULL b3 = pack_dup(bv.w);
            const float* arow = Ac + kk * AROWS;
#pragma unroll
            for (int i = 0; i < 8; ++i) {
                ULL a = *(const ULL*)(arow + 2 * i);
                fma2(acc[i][0], a, b0);
                fma2(acc[i][1], a, b1);
                fma2(acc[i][2], a, b2);
                fma2(acc[i][3], a, b3);
            }
        }

        // stage next tile
        if (kt < D / BK - 1) {
            float* An = As + (s ^ 1) * A_STG;
            float* Bn = Bs + (s ^ 1) * B_STG;
#pragma unroll
            for (int g = 0; g < 4; ++g) {
                const int m = ar + g * 64;
                An[(aq * 4 + 0) * AROWS + m] = ra[g].x;
                An[(aq * 4 + 1) * AROWS + m] = ra[g].y;
                An[(aq * 4 + 2) * AROWS + m] = ra[g].z;
                An[(aq * 4 + 3) * AROWS + m] = ra[g].w;
            }
            Bn[(bq * 4 + 0) * BROWS + bn] = rb.x;
            Bn[(bq * 4 + 1) * BROWS + bn] = rb.y;
            Bn[(bq * 4 + 2) * BROWS + bn] = rb.z;
            Bn[(bq * 4 + 3) * BROWS + bn] = rb.w;
        }
        __syncthreads();
    }

    // ---- epilogue: unpack m-pairs, store to g_ext [t][b][o] ----
    // BM=256 aligned: all rows in this tile share b-block boundaries cleanly.
#pragma unroll
    for (int i = 0; i < 8; ++i) {
        float lo[4], hi[4];
#pragma unroll
        for (int j = 0; j < 4; ++j) unpack2(acc[i][j], lo[j], hi[j]);
        const int m = Mb + m0 + 2 * i;
        const int b0i = m >> 9, t0i = m & 511;
        const int b1i = (m + 1) >> 9, t1i = (m + 1) & 511;
        *(float4*)&g_ext[((size_t)t0i * BATCH + b0i) * D + Nb + n0] = make_float4(lo[0], lo[1], lo[2], lo[3]);
        *(float4*)&g_ext[((size_t)t1i * BATCH + b1i) * D + Nb + n0] = make_float4(hi[0], hi[1], hi[2], hi[3]);
    }
}

// ---------------- Phase B: persistent recurrence, W_rec in registers ----------------
// (unchanged from round 7 — measured at its fma floor)
#define NTILE 32
#define MTILE 16
#define SSTR  1028
#define PERS_SMEM ((MTILE * SSTR + 8 * 512) * 4)   // 82176 B

__global__ __launch_bounds__(256, 1) void rnn_persistent(const float* __restrict__ Wr) {
    extern __shared__ float sm[];
    float* sTile = sm;                   // [16][SSTR]
    float* red   = sm + MTILE * SSTR;    // [8 kgroups][16 m * 32 n]

    const int tid = threadIdx.x;
    const int w   = tid >> 5;            // warp = 128-wide k-slice (0..7)
    const int l   = tid & 31;            // lane = n
    const int Nb  = blockIdx.x * NTILE;
    const int Mb  = blockIdx.y * MTILE;
    unsigned* bar = &g_bars[blockIdx.y * 32];

    const int r  = tid >> 4;             // staging row 0..15
    const int c0 = tid & 15;             // float4 column base

    ULL w2[64];
    {
        const float* wp = Wr + (size_t)(Nb + l) * D + w * 128;
#pragma unroll
        for (int j = 0; j < 32; ++j) {
            ulonglong2 v = *(const ulonglong2*)(wp + 4 * j);
            w2[2 * j]     = v.x;
            w2[2 * j + 1] = v.y;
        }
    }

    {
        const float4* esrc = (const float4*)(g_ext + (size_t)(Mb + r) * D);
        float* sdst = sTile + r * SSTR;
#pragma unroll
        for (int j = 0; j < 16; ++j) {
            const int q = c0 + j * 16;
            *(float4*)(sdst + q * 4) = __ldg(esrc + q);
        }
    }
    __syncthreads();

    for (int t = 0; t < TLEN; ++t) {
        float* sout = (t & 1) ? g_stateA : g_stateB;

        if (t > 0) {
            const float* sin = (t & 1) ? g_stateB : g_stateA;
            if (tid == 0) {
                const unsigned target = 32u * (unsigned)t;
                unsigned v;
                do {
                    asm volatile("ld.acquire.gpu.u32 %0, [%1];" : "=r"(v) : "l"(bar));
                } while (v < target);
            }
            __syncthreads();

            const float4* ssrc = (const float4*)(sin + (size_t)(Mb + r) * D);
            float* sdst = sTile + r * SSTR;
#pragma unroll
            for (int j = 0; j < 16; j += 2) {
                const int q0 = c0 + j * 16;
                const int q1 = c0 + (j + 1) * 16;
                float4 a0 = __ldcg(ssrc + q0);
                float4 a1 = __ldcg(ssrc + q1);
                float4 b0 = *(const float4*)(sdst + q0 * 4);
                float4 b1 = *(const float4*)(sdst + q1 * 4);
                *(float4*)(sdst + q0 * 4) = make_float4(a0.x + b0.x, a0.y + b0.y, a0.z + b0.z, a0.w + b0.w);
                *(float4*)(sdst + q1 * 4) = make_float4(a1.x + b1.x, a1.y + b1.y, a1.z + b1.z, a1.w + b1.w);
            }
            __syncthreads();
        }

        ULL acc[16];
#pragma unroll
        for (int i = 0; i < 16; ++i) acc[i] = 0ULL;

        const float* sb = sTile + w * 128;
#pragma unroll
        for (int m = 0; m < 16; ++m) {
            const ulonglong2* srow = (const ulonglong2*)(sb + (size_t)m * SSTR);
#pragma unroll
            for (int j = 0; j < 32; ++j) {
                ulonglong2 sv = srow[j];
                fma2(acc[m], sv.x, w2[2 * j]);
                fma2(acc[m], sv.y, w2[2 * j + 1]);
            }
        }

#pragma unroll
        for (int m = 0; m < 16; ++m) {
            float lo, hi;
            unpack2(acc[m], lo, hi);
            red[w * 512 + m * 32 + l] = lo + hi;
        }
        __syncthreads();

#pragma unroll
        for (int rep = 0; rep < 2; ++rep) {
            const int idx = tid + rep * 256;
            const int rm = idx >> 5, rn = idx & 31;
            float s0 = 0.f, s1 = 0.f;
#pragma unroll
            for (int g = 0; g < 8; g += 2) {
                s0 += red[g * 512 + idx];
                s1 += red[(g + 1) * 512 + idx];
            }
            __stcg(&sout[(size_t)(Mb + rm) * D + Nb + rn], fmaxf(s0 + s1, 0.f));
        }
        __syncthreads();

        if (tid == 0) {
            __threadfence();
            atomicAdd(bar, 1u);
        }
        if (t + 1 < TLEN) {
            const float4* esrc = (const float4*)(g_ext + (size_t)(t + 1) * (BATCH * D) + (size_t)(Mb + r) * D);
            float* sdst = sTile + r * SSTR;
#pragma unroll
            for (int j = 0; j < 16; ++j) {
                const int q = c0 + j * 16;
                *(float4*)(sdst + q * 4) = __ldg(esrc + q);
            }
        }
    }
}

// ---------------- final: out[:,0,:] = final state ----------------
__global__ void final_copy_kernel(float* __restrict__ out) {
    const int i = blockIdx.x * blockDim.x + threadIdx.x;   // < 65536
    const int b = i >> 10, o = i & 1023;
    out[(size_t)b * (TLEN * D) + o] = g_stateA[i];
}

// ---------------- launch ----------------
extern "C" void kernel_launch(void* const* d_in, const int* in_sizes, int n_in,
                              void* d_out, int out_size) {
    const float* x     = (const float*)d_in[0];
    const float* W_in  = (const float*)d_in[1];
    const float* W_rec = (const float*)d_in[2];
    float* out = (float*)d_out;

    cudaFuncSetAttribute(rnn_persistent, cudaFuncAttributeMaxDynamicSharedMemorySize, PERS_SMEM);
    cudaFuncSetAttribute(ext_gemm_kernel, cudaFuncAttributeMaxDynamicSharedMemorySize, EXT_SMEM);

    // zero output (poisoned by harness), initial state, barrier counters
    zero4_kernel<<<(BATCH * TLEN * D / 4 + 255) / 256, 256>>>((float4*)out, BATCH * TLEN * D / 4);
    zero_state_kernel<<<(BATCH * D + 255) / 256, 256>>>();

    // Phase A: input projections for all timesteps (ext layout [t][b][o])
    ext_gemm_kernel<<<dim3(D / BN, (BATCH * TLEN) / BM), 256, EXT_SMEM>>>(x, W_in);

    // Phase B: full recurrence in one persistent kernel
    rnn_persistent<<<dim3(D / NTILE, BATCH / MTILE), 256, PERS_SMEM>>>(W_rec);

    // write final state into out[:,0,:]
    final_copy_kernel<<<(BATCH * D) / 256, 256>>>(out);
}